// round 4
// baseline (speedup 1.0000x reference)
#include <cuda_runtime.h>
#include <cstdint>

#define S_LEN 128
#define B_SZ  32
#define H_DIM 512
#define V_SZ  10000

// ---------------- scratch (device globals; no allocation allowed) ----------------
__device__ float g_X[S_LEN * B_SZ * H_DIM];       // layer input / tops (8 MB)
__device__ float g_Y[S_LEN * B_SZ * H_DIM];       // layer-0 outputs (8 MB)
__device__ float g_A[S_LEN * B_SZ * 3 * H_DIM];   // precomputed x@Wx+bx (24 MB)
__device__ float g_hT[H_DIM * B_SZ];              // h transposed [k][b]
__device__ float g_rhT[H_DIM * B_SZ];             // r*h transposed [k][b]
__device__ float g_zT[H_DIM * B_SZ];              // z transposed [o][b]
__device__ int   g_is64;

// ---------------- two-level grid barrier (64 CTAs, bounded spin) ----------------
#define NCTA 64
#define NGRP 8
__device__ unsigned g_cnt[NGRP * 32];   // one counter per 128B line
__device__ unsigned g_top;
__device__ volatile unsigned g_gen;

__device__ __forceinline__ void grid_barrier() {
    __syncthreads();
    if (threadIdx.x == 0) {
        unsigned gen = g_gen;
        __threadfence();
        unsigned grp = blockIdx.x >> 3;          // 8 CTAs per group
        if (atomicAdd(&g_cnt[grp * 32], 1u) == 7u) {
            if (atomicAdd(&g_top, 1u) == NGRP - 1u) {
                g_top = 0;
                #pragma unroll
                for (int i = 0; i < NGRP; i++) g_cnt[i * 32] = 0;
                __threadfence();
                g_gen = gen + 1;
            }
        }
        // bounded spin: never hangs the container even if co-residency breaks
        unsigned it = 0;
        while (g_gen == gen) {
            ++it;
            if (it > 4096u) { __nanosleep(64); }
            if (it > 200000u) break;
        }
        __threadfence();
    }
    __syncthreads();
}

// ---------------- token dtype detector ----------------
__global__ void detect_kernel(const int* __restrict__ t32) {
    if (threadIdx.x == 0 && blockIdx.x == 0) {
        unsigned o = 0;
        for (int i = 0; i < 128; i++) o |= (unsigned)t32[2 * i + 1];
        g_is64 = (o == 0) ? 1 : 0;   // all high words zero -> int64
    }
}

// ---------------- embedding gather (dtype-robust, clamped) ----------------
__global__ void embed_kernel(const void* __restrict__ tok,
                             const float* __restrict__ emb,
                             float* __restrict__ X) {
    int row = blockIdx.x;                       // row = s*B + b
    long long t;
    if (g_is64) t = ((const long long*)tok)[row];
    else        t = (long long)((const int*)tok)[row];
    if (t < 0) t = 0;
    if (t >= V_SZ) t = V_SZ - 1;
    const float4* src = (const float4*)(emb + (size_t)t * H_DIM);
    float4* dst = (float4*)(X + (size_t)row * H_DIM);
    for (int i = threadIdx.x; i < H_DIM / 4; i += blockDim.x) dst[i] = src[i];
}

// ---------------- tf32 mma GEMM: C[M,N] = A[M,K] * op(B) + bias ----------------
#define BM 128
#define BN 128
#define BKK 16
#define AST 20
#define BST_KN 136
#define BST_NK 20

__device__ __forceinline__ unsigned f2tf(float x) {
    unsigned r; asm("cvt.rna.tf32.f32 %0, %1;" : "=r"(r) : "f"(x)); return r;
}
__device__ __forceinline__ void mma8(float* c, const unsigned* a, const unsigned* b) {
    asm volatile(
        "mma.sync.aligned.m16n8k8.row.col.f32.tf32.tf32.f32 "
        "{%0,%1,%2,%3}, {%4,%5,%6,%7}, {%8,%9}, {%0,%1,%2,%3};\n"
        : "+f"(c[0]), "+f"(c[1]), "+f"(c[2]), "+f"(c[3])
        : "r"(a[0]), "r"(a[1]), "r"(a[2]), "r"(a[3]), "r"(b[0]), "r"(b[1]));
}

template <bool BT>
__global__ __launch_bounds__(256)
void gemm_tf32(const float* __restrict__ A, int lda,
               const float* __restrict__ Bm, int ldb,
               const float* __restrict__ bias,
               float* __restrict__ C, int ldc,
               int M, int N, int K) {
    __shared__ float As[BM * AST];
    __shared__ float Bs[2560];

    int tid = threadIdx.x;
    int lane = tid & 31, warp = tid >> 5;
    int wr = warp >> 2, wc = warp & 3;
    int m0 = blockIdx.y * BM, n0 = blockIdx.x * BN;

    float c[4][4][4];
    #pragma unroll
    for (int i = 0; i < 4; i++)
        #pragma unroll
        for (int j = 0; j < 4; j++)
            #pragma unroll
            for (int k = 0; k < 4; k++) c[i][j][k] = 0.f;

    for (int kk = 0; kk < K; kk += BKK) {
        __syncthreads();
        {
            int r = tid >> 1, half = tid & 1;
            const float4* src = (const float4*)(A + (size_t)(m0 + r) * lda + kk + half * 8);
            float4 v0 = src[0], v1 = src[1];
            *(float4*)&As[r * AST + half * 8]     = v0;
            *(float4*)&As[r * AST + half * 8 + 4] = v1;
        }
        if (BT) {
            int r = tid >> 1, half = tid & 1;
            int gn = n0 + r;
            float4 v0 = make_float4(0.f, 0.f, 0.f, 0.f), v1 = v0;
            if (gn < N) {
                const float4* src = (const float4*)(Bm + (size_t)gn * ldb + kk + half * 8);
                v0 = src[0]; v1 = src[1];
            }
            *(float4*)&Bs[r * BST_NK + half * 8]     = v0;
            *(float4*)&Bs[r * BST_NK + half * 8 + 4] = v1;
        } else {
            int kr = tid >> 4, cs = tid & 15;
            const float4* src = (const float4*)(Bm + (size_t)(kk + kr) * ldb + n0 + cs * 8);
            *(float4*)&Bs[kr * BST_KN + cs * 8]     = src[0];
            *(float4*)&Bs[kr * BST_KN + cs * 8 + 4] = src[1];
        }
        __syncthreads();

        int ar = lane >> 2, ak = lane & 3;
        #pragma unroll
        for (int kq = 0; kq < BKK; kq += 8) {
            unsigned af[4][4], bf[4][2];
            #pragma unroll
            for (int mt = 0; mt < 4; mt++) {
                int rb = wr * 64 + mt * 16;
                af[mt][0] = f2tf(As[(rb + ar)     * AST + kq + ak]);
                af[mt][1] = f2tf(As[(rb + ar + 8) * AST + kq + ak]);
                af[mt][2] = f2tf(As[(rb + ar)     * AST + kq + ak + 4]);
                af[mt][3] = f2tf(As[(rb + ar + 8) * AST + kq + ak + 4]);
            }
            #pragma unroll
            for (int nt = 0; nt < 4; nt++) {
                int cb = wc * 32 + nt * 8 + (lane >> 2);
                if (BT) {
                    bf[nt][0] = f2tf(Bs[cb * BST_NK + kq + ak]);
                    bf[nt][1] = f2tf(Bs[cb * BST_NK + kq + ak + 4]);
                } else {
                    bf[nt][0] = f2tf(Bs[(kq + ak)     * BST_KN + cb]);
                    bf[nt][1] = f2tf(Bs[(kq + ak + 4) * BST_KN + cb]);
                }
            }
            #pragma unroll
            for (int mt = 0; mt < 4; mt++)
                #pragma unroll
                for (int nt = 0; nt < 4; nt++)
                    mma8(c[mt][nt], af[mt], bf[nt]);
        }
    }

    #pragma unroll
    for (int mt = 0; mt < 4; mt++) {
        #pragma unroll
        for (int nt = 0; nt < 4; nt++) {
            int r0 = m0 + wr * 64 + mt * 16 + (lane >> 2);
            int cc = n0 + wc * 32 + nt * 8 + (lane & 3) * 2;
            if (cc < N) {
                float bv = bias[cc];
                C[(size_t)r0 * ldc + cc]       = c[mt][nt][0] + bv;
                C[(size_t)(r0 + 8) * ldc + cc] = c[mt][nt][2] + bv;
            }
            if (cc + 1 < N) {
                float bv = bias[cc + 1];
                C[(size_t)r0 * ldc + cc + 1]       = c[mt][nt][1] + bv;
                C[(size_t)(r0 + 8) * ldc + cc + 1] = c[mt][nt][3] + bv;
            }
        }
    }
}

// ---------------- persistent GRU recurrence (one layer, 64 CTAs) ----------------
// warp = output column o (512 warps), lane = batch b.
// smem: hS [512][32] snapshot of h^T (phase1) / (r*h)^T (phase2);
//       U0s/U1s/U2s [512][9] this CTA's 8 U-columns (staged once).
__global__ __launch_bounds__(256)
void recur_kernel(const float* __restrict__ A, const float* __restrict__ U,
                  const float* __restrict__ h0, float* __restrict__ Y,
                  float* __restrict__ h_final) {
    extern __shared__ float smem[];
    float* hS  = smem;                 // 16384 floats
    float* U0s = smem + 16384;         // 512*9
    float* U1s = U0s + 4608;
    float* U2s = U1s + 4608;

    int tid = threadIdx.x, lane = tid & 31, w = tid >> 5;
    const int o = blockIdx.x * 8 + w;  // 0..511

    // stage this CTA's U columns once (o block = blockIdx*8 .. +7)
    for (int i = tid; i < 4096; i += 256) {
        int k = i >> 3, ww = i & 7;
        int col = blockIdx.x * 8 + ww;
        U0s[k * 9 + ww] = U[(size_t)k * H_DIM + col];
        U1s[k * 9 + ww] = U[(size_t)H_DIM * H_DIM + k * H_DIM + col];
        U2s[k * 9 + ww] = U[(size_t)2 * H_DIM * H_DIM + k * H_DIM + col];
    }

    // init h^T from h0 [B][H]
    for (int idx = blockIdx.x * 256 + tid; idx < B_SZ * H_DIM; idx += NCTA * 256) {
        int b = idx >> 9, k = idx & 511;
        g_hT[k * B_SZ + b] = h0[idx];
    }
    grid_barrier();

    for (int t = 0; t < S_LEN; ++t) {
        // ---- stage h^T snapshot into smem ----
        for (int i = tid; i < (B_SZ * H_DIM) / 4; i += 256)
            ((float4*)hS)[i] = __ldcg(((const float4*)g_hT) + i);
        __syncthreads();

        // ---- phase 1: r and z for (o, all b) ----
        {
            float a0 = 0.f, a1 = 0.f;
            for (int kc = 0; kc < H_DIM; kc += 32) {
                float u0r = U0s[(kc + lane) * 9 + w];
                float u1r = U1s[(kc + lane) * 9 + w];
                #pragma unroll 8
                for (int j = 0; j < 32; j++) {
                    float hv = hS[(kc + j) * 32 + lane];
                    a0 = fmaf(__shfl_sync(0xffffffffu, u0r, j), hv, a0);
                    a1 = fmaf(__shfl_sync(0xffffffffu, u1r, j), hv, a1);
                }
            }
            const float* Ar = A + (size_t)(t * B_SZ + lane) * 3 * H_DIM + o;
            float r = 1.f / (1.f + __expf(-(a0 + Ar[0])));
            float z = 1.f / (1.f + __expf(-(a1 + Ar[H_DIM])));
            float hv = hS[o * 32 + lane];          // h[b][o]
            __stcg(&g_rhT[o * 32 + lane], r * hv);
            __stcg(&g_zT[o * 32 + lane], z);
        }
        grid_barrier();

        // ---- stage (r*h)^T snapshot into smem ----
        for (int i = tid; i < (B_SZ * H_DIM) / 4; i += 256)
            ((float4*)hS)[i] = __ldcg(((const float4*)g_rhT) + i);
        __syncthreads();

        // ---- phase 2: candidate + state update ----
        {
            float a2 = 0.f;
            for (int kc = 0; kc < H_DIM; kc += 32) {
                float u2r = U2s[(kc + lane) * 9 + w];
                #pragma unroll 8
                for (int j = 0; j < 32; j++) {
                    float hv = hS[(kc + j) * 32 + lane];
                    a2 = fmaf(__shfl_sync(0xffffffffu, u2r, j), hv, a2);
                }
            }
            const float* Ac = A + ((size_t)(t * B_SZ + lane) * 3 + 2) * H_DIM + o;
            float hh = tanhf(a2 + Ac[0]);
            float z  = __ldcg(&g_zT[o * 32 + lane]);
            float ho = __ldcg(&g_hT[o * 32 + lane]);
            float hn = fmaf(z, hh - ho, ho);
            __stcg(&g_hT[o * 32 + lane], hn);
            Y[(size_t)(t * B_SZ + lane) * H_DIM + o] = hn;
        }
        grid_barrier();
    }

    // final hidden state [B][H]
    for (int idx = blockIdx.x * 256 + tid; idx < B_SZ * H_DIM; idx += NCTA * 256)
        h_final[idx] = __ldcg(&g_hT[(idx & 511) * 32 + (idx >> 9)]);
}

// ---------------- launch ----------------
extern "C" void kernel_launch(void* const* d_in, const int* in_sizes, int n_in,
                              void* d_out, int out_size) {
    const void*  tokens = d_in[0];
    const float* h0  = (const float*)d_in[1];
    const float* emb = (const float*)d_in[2];
    const float* Wx  = (const float*)d_in[3];
    const float* bx  = (const float*)d_in[4];
    const float* U   = (const float*)d_in[5];
    const float* Wy  = (const float*)d_in[6];
    const float* by  = (const float*)d_in[7];

    float* logits = (float*)d_out;                              // [S,B,V]
    float* hfin   = logits + (size_t)S_LEN * B_SZ * V_SZ;       // [L,B,H]

    float *dX, *dY, *dA;
    cudaGetSymbolAddress((void**)&dX, g_X);
    cudaGetSymbolAddress((void**)&dY, g_Y);
    cudaGetSymbolAddress((void**)&dA, g_A);

    const int M = S_LEN * B_SZ;
    const int RSMEM = (16384 + 3 * 4608) * 4;   // 120832 bytes
    cudaFuncSetAttribute(recur_kernel, cudaFuncAttributeMaxDynamicSharedMemorySize, RSMEM);

    dim3 blk(256);

    // 0) token dtype detection
    detect_kernel<<<1, 32>>>((const int*)tokens);

    // 1) embeddings -> g_X
    embed_kernel<<<M, 128>>>(tokens, emb, dX);

    // 2) A0 = X @ Wx[0] + bx[0]  (3 gate GEMMs into interleaved [S,B,3,H])
    for (int g = 0; g < 3; g++)
        gemm_tf32<false><<<dim3(4, M / 128), blk>>>(
            dX, H_DIM, Wx + (size_t)g * H_DIM * H_DIM, H_DIM,
            bx + g * H_DIM, dA + g * H_DIM, 3 * H_DIM, M, H_DIM, H_DIM);

    // 3) layer-0 recurrence -> g_Y, h_final[0]
    recur_kernel<<<NCTA, 256, RSMEM>>>(dA, U, h0, dY, hfin);

    // 4) A1 = Y @ Wx[1] + bx[1]
    for (int g = 0; g < 3; g++)
        gemm_tf32<false><<<dim3(4, M / 128), blk>>>(
            dY, H_DIM, Wx + (size_t)(3 + g) * H_DIM * H_DIM, H_DIM,
            bx + (3 + g) * H_DIM, dA + g * H_DIM, 3 * H_DIM, M, H_DIM, H_DIM);

    // 5) layer-1 recurrence -> g_X (tops), h_final[1]
    recur_kernel<<<NCTA, 256, RSMEM>>>(dA, U + (size_t)3 * H_DIM * H_DIM,
                                       h0 + B_SZ * H_DIM, dX, hfin + B_SZ * H_DIM);

    // 6) logits = tops @ Wy^T + by
    gemm_tf32<true><<<dim3((V_SZ + 127) / 128, M / 128), blk>>>(
        dX, H_DIM, Wy, H_DIM, by, logits, V_SZ, M, V_SZ, H_DIM);
}

// round 5
// speedup vs baseline: 1.5884x; 1.5884x over previous
#include <cuda_runtime.h>
#include <cstdint>

#define S_LEN 128
#define B_SZ  32
#define H_DIM 512
#define V_SZ  10000

// ---------------- scratch (device globals; no allocation allowed) ----------------
__device__ float g_X[S_LEN * B_SZ * H_DIM];       // layer input / tops (8 MB)
__device__ float g_Y[S_LEN * B_SZ * H_DIM];       // layer-0 outputs (8 MB)
__device__ float g_A[S_LEN * B_SZ * 3 * H_DIM];   // precomputed x@Wx+bx (24 MB)
__device__ float g_h[B_SZ * H_DIM];               // h  [b][k]
__device__ float g_rh[B_SZ * H_DIM];              // r*h [b][k]
__device__ int   g_is64;

// ---------------- per-batch-group grid barrier (32 CTAs each, flat) -------------
__device__ unsigned          g_cnt2[4 * 32];
__device__ volatile unsigned g_gen2[4 * 32];

__device__ __forceinline__ void bg_barrier(int bg) {
    __syncthreads();
    if (threadIdx.x == 0) {
        volatile unsigned* genp = &g_gen2[bg * 32];
        unsigned* cntp = &g_cnt2[bg * 32];
        unsigned gen = *genp;
        __threadfence();
        if (atomicAdd(cntp, 1u) == 31u) {
            *cntp = 0;
            __threadfence();
            *genp = gen + 1;
        } else {
            unsigned it = 0;
            while (*genp == gen) {
                if (++it > 65536u) { __nanosleep(32); }
                if (it > 400000u) break;   // safety valve: terminate, never hang
            }
        }
        __threadfence();
    }
    __syncthreads();
}

// ---------------- token dtype detector ----------------
__global__ void detect_kernel(const int* __restrict__ t32) {
    if (threadIdx.x == 0 && blockIdx.x == 0) {
        unsigned o = 0;
        for (int i = 0; i < 128; i++) o |= (unsigned)t32[2 * i + 1];
        g_is64 = (o == 0) ? 1 : 0;   // all high words zero -> int64
    }
}

// ---------------- embedding gather (dtype-robust, clamped) ----------------
__global__ void embed_kernel(const void* __restrict__ tok,
                             const float* __restrict__ emb,
                             float* __restrict__ X) {
    int row = blockIdx.x;
    long long t;
    if (g_is64) t = ((const long long*)tok)[row];
    else        t = (long long)((const int*)tok)[row];
    if (t < 0) t = 0;
    if (t >= V_SZ) t = V_SZ - 1;
    const float4* src = (const float4*)(emb + (size_t)t * H_DIM);
    float4* dst = (float4*)(X + (size_t)row * H_DIM);
    for (int i = threadIdx.x; i < H_DIM / 4; i += blockDim.x) dst[i] = src[i];
}

// ---------------- tf32 mma helpers ----------------
#define BM 128
#define BN 128
#define BKK 16
#define AST 20
#define BST_KN 136
#define BST_NK 20

__device__ __forceinline__ unsigned f2tf(float x) {
    unsigned r; asm("cvt.rna.tf32.f32 %0, %1;" : "=r"(r) : "f"(x)); return r;
}
__device__ __forceinline__ void mma8(float* c, const unsigned* a, const unsigned* b) {
    asm volatile(
        "mma.sync.aligned.m16n8k8.row.col.f32.tf32.tf32.f32 "
        "{%0,%1,%2,%3}, {%4,%5,%6,%7}, {%8,%9}, {%0,%1,%2,%3};\n"
        : "+f"(c[0]), "+f"(c[1]), "+f"(c[2]), "+f"(c[3])
        : "r"(a[0]), "r"(a[1]), "r"(a[2]), "r"(a[3]), "r"(b[0]), "r"(b[1]));
}

// ---------- fused 3-gate input GEMM: g_A[row][g*512+o] = X@Wx[g] + bx[g] --------
__global__ __launch_bounds__(256)
void gemm_ax(const float* __restrict__ A,          // X [M,512]
             const float* __restrict__ Wxl,        // [3,512,512]
             const float* __restrict__ bxl,        // [3,512]
             float* __restrict__ C) {              // [M,1536]
    __shared__ float As[BM * AST];
    __shared__ float Bs[BKK * BST_KN];

    int tid = threadIdx.x;
    int lane = tid & 31, warp = tid >> 5;
    int wr = warp >> 2, wc = warp & 3;
    int m0 = blockIdx.y * BM, n0 = blockIdx.x * BN;
    int g = n0 >> 9, col0 = n0 & 511;
    const float* Bg = Wxl + (size_t)g * H_DIM * H_DIM;

    float c[4][4][4];
    #pragma unroll
    for (int i = 0; i < 4; i++)
        #pragma unroll
        for (int j = 0; j < 4; j++)
            #pragma unroll
            for (int k = 0; k < 4; k++) c[i][j][k] = 0.f;

    for (int kk = 0; kk < H_DIM; kk += BKK) {
        __syncthreads();
        {
            int r = tid >> 1, half = tid & 1;
            const float4* src = (const float4*)(A + (size_t)(m0 + r) * H_DIM + kk + half * 8);
            float4 v0 = src[0], v1 = src[1];
            *(float4*)&As[r * AST + half * 8]     = v0;
            *(float4*)&As[r * AST + half * 8 + 4] = v1;
        }
        {
            int kr = tid >> 4, cs = tid & 15;
            const float4* src = (const float4*)(Bg + (size_t)(kk + kr) * H_DIM + col0 + cs * 8);
            *(float4*)&Bs[kr * BST_KN + cs * 8]     = src[0];
            *(float4*)&Bs[kr * BST_KN + cs * 8 + 4] = src[1];
        }
        __syncthreads();

        int ar = lane >> 2, ak = lane & 3;
        #pragma unroll
        for (int kq = 0; kq < BKK; kq += 8) {
            unsigned af[4][4], bf[4][2];
            #pragma unroll
            for (int mt = 0; mt < 4; mt++) {
                int rb = wr * 64 + mt * 16;
                af[mt][0] = f2tf(As[(rb + ar)     * AST + kq + ak]);
                af[mt][1] = f2tf(As[(rb + ar + 8) * AST + kq + ak]);
                af[mt][2] = f2tf(As[(rb + ar)     * AST + kq + ak + 4]);
                af[mt][3] = f2tf(As[(rb + ar + 8) * AST + kq + ak + 4]);
            }
            #pragma unroll
            for (int nt = 0; nt < 4; nt++) {
                int cb = wc * 32 + nt * 8 + (lane >> 2);
                bf[nt][0] = f2tf(Bs[(kq + ak)     * BST_KN + cb]);
                bf[nt][1] = f2tf(Bs[(kq + ak + 4) * BST_KN + cb]);
            }
            #pragma unroll
            for (int mt = 0; mt < 4; mt++)
                #pragma unroll
                for (int nt = 0; nt < 4; nt++)
                    mma8(c[mt][nt], af[mt], bf[nt]);
        }
    }

    #pragma unroll
    for (int mt = 0; mt < 4; mt++) {
        #pragma unroll
        for (int nt = 0; nt < 4; nt++) {
            int r0 = m0 + wr * 64 + mt * 16 + (lane >> 2);
            int cc = n0 + wc * 32 + nt * 8 + (lane & 3) * 2;
            float bv0 = bxl[g * H_DIM + (cc & 511)];
            float bv1 = bxl[g * H_DIM + ((cc + 1) & 511)];
            C[(size_t)r0 * 1536 + cc]           = c[mt][nt][0] + bv0;
            C[(size_t)r0 * 1536 + cc + 1]       = c[mt][nt][1] + bv1;
            C[(size_t)(r0 + 8) * 1536 + cc]     = c[mt][nt][2] + bv0;
            C[(size_t)(r0 + 8) * 1536 + cc + 1] = c[mt][nt][3] + bv1;
        }
    }
}

// ---------------- logits GEMM: C[M,N] = A[M,K] * B^T + bias (B:[N,K]) ----------
__global__ __launch_bounds__(256)
void gemm_bt(const float* __restrict__ A,
             const float* __restrict__ Bm,
             const float* __restrict__ bias,
             float* __restrict__ C, int N) {
    __shared__ float As[BM * AST];
    __shared__ float Bs[BM * BST_NK];

    int tid = threadIdx.x;
    int lane = tid & 31, warp = tid >> 5;
    int wr = warp >> 2, wc = warp & 3;
    int m0 = blockIdx.y * BM, n0 = blockIdx.x * BN;

    float c[4][4][4];
    #pragma unroll
    for (int i = 0; i < 4; i++)
        #pragma unroll
        for (int j = 0; j < 4; j++)
            #pragma unroll
            for (int k = 0; k < 4; k++) c[i][j][k] = 0.f;

    for (int kk = 0; kk < H_DIM; kk += BKK) {
        __syncthreads();
        {
            int r = tid >> 1, half = tid & 1;
            const float4* src = (const float4*)(A + (size_t)(m0 + r) * H_DIM + kk + half * 8);
            float4 v0 = src[0], v1 = src[1];
            *(float4*)&As[r * AST + half * 8]     = v0;
            *(float4*)&As[r * AST + half * 8 + 4] = v1;
        }
        {
            int r = tid >> 1, half = tid & 1;
            int gn = n0 + r;
            float4 v0 = make_float4(0.f, 0.f, 0.f, 0.f), v1 = v0;
            if (gn < N) {
                const float4* src = (const float4*)(Bm + (size_t)gn * H_DIM + kk + half * 8);
                v0 = src[0]; v1 = src[1];
            }
            *(float4*)&Bs[r * BST_NK + half * 8]     = v0;
            *(float4*)&Bs[r * BST_NK + half * 8 + 4] = v1;
        }
        __syncthreads();

        int ar = lane >> 2, ak = lane & 3;
        #pragma unroll
        for (int kq = 0; kq < BKK; kq += 8) {
            unsigned af[4][4], bf[4][2];
            #pragma unroll
            for (int mt = 0; mt < 4; mt++) {
                int rb = wr * 64 + mt * 16;
                af[mt][0] = f2tf(As[(rb + ar)     * AST + kq + ak]);
                af[mt][1] = f2tf(As[(rb + ar + 8) * AST + kq + ak]);
                af[mt][2] = f2tf(As[(rb + ar)     * AST + kq + ak + 4]);
                af[mt][3] = f2tf(As[(rb + ar + 8) * AST + kq + ak + 4]);
            }
            #pragma unroll
            for (int nt = 0; nt < 4; nt++) {
                int cb = wc * 32 + nt * 8 + (lane >> 2);
                bf[nt][0] = f2tf(Bs[cb * BST_NK + kq + ak]);
                bf[nt][1] = f2tf(Bs[cb * BST_NK + kq + ak + 4]);
            }
            #pragma unroll
            for (int mt = 0; mt < 4; mt++)
                #pragma unroll
                for (int nt = 0; nt < 4; nt++)
                    mma8(c[mt][nt], af[mt], bf[nt]);
        }
    }

    #pragma unroll
    for (int mt = 0; mt < 4; mt++) {
        #pragma unroll
        for (int nt = 0; nt < 4; nt++) {
            int r0 = m0 + wr * 64 + mt * 16 + (lane >> 2);
            int cc = n0 + wc * 32 + nt * 8 + (lane & 3) * 2;
            if (cc < N) {
                float bv = bias[cc];
                C[(size_t)r0 * N + cc]       = c[mt][nt][0] + bv;
                C[(size_t)(r0 + 8) * N + cc] = c[mt][nt][2] + bv;
            }
            if (cc + 1 < N) {
                float bv = bias[cc + 1];
                C[(size_t)r0 * N + cc + 1]       = c[mt][nt][1] + bv;
                C[(size_t)(r0 + 8) * N + cc + 1] = c[mt][nt][3] + bv;
            }
        }
    }
}

// ---------------- persistent GRU recurrence (one layer, 128 CTAs) ----------------
// CTA = (bg 0..3, og 0..31): 8 batches x 16 outputs. lane = (o_loc 0..3, b_loc 0..7).
// smem: Ur/Uz/Uc [16 o][516] transposed U; hS [8 b][516]; zS [8][17]; redS [128].
#define HSS 516
__global__ __launch_bounds__(256)
void recur_kernel(const float* __restrict__ A, const float* __restrict__ U,
                  const float* __restrict__ h0, float* __restrict__ Y,
                  float* __restrict__ h_final) {
    extern __shared__ float smem[];
    float* Ur = smem;                   // 16*516
    float* Uz = Ur + 16 * HSS;
    float* Uc = Uz + 16 * HSS;
    float* hS = Uc + 16 * HSS;          // 8*516
    float* zS = hS + 8 * HSS;           // 8*17
    float* redS = zS + 136;             // 128

    const int tid = threadIdx.x, lane = tid & 31, w = tid >> 5;
    const int b_loc = lane & 7, o_loc = lane >> 3;
    const int og = blockIdx.x & 31, bg = blockIdx.x >> 5;
    const int o_idx = (w & 3) * 4 + o_loc;       // 0..15
    const int o = og * 16 + o_idx;
    const int b = bg * 8 + b_loc;

    // ---- stage transposed U columns (once): Us[o_idx][i] = U[g][i][og*16+o_idx]
    for (int idx = tid; idx < 2048; idx += 256) {
        int i = idx >> 2, o4 = idx & 3;
        float4 v0 = *(const float4*)(U + (size_t)i * H_DIM + og * 16 + o4 * 4);
        float4 v1 = *(const float4*)(U + (size_t)H_DIM * H_DIM + (size_t)i * H_DIM + og * 16 + o4 * 4);
        float4 v2 = *(const float4*)(U + (size_t)2 * H_DIM * H_DIM + (size_t)i * H_DIM + og * 16 + o4 * 4);
        Ur[(o4 * 4 + 0) * HSS + i] = v0.x; Ur[(o4 * 4 + 1) * HSS + i] = v0.y;
        Ur[(o4 * 4 + 2) * HSS + i] = v0.z; Ur[(o4 * 4 + 3) * HSS + i] = v0.w;
        Uz[(o4 * 4 + 0) * HSS + i] = v1.x; Uz[(o4 * 4 + 1) * HSS + i] = v1.y;
        Uz[(o4 * 4 + 2) * HSS + i] = v1.z; Uz[(o4 * 4 + 3) * HSS + i] = v1.w;
        Uc[(o4 * 4 + 0) * HSS + i] = v2.x; Uc[(o4 * 4 + 1) * HSS + i] = v2.y;
        Uc[(o4 * 4 + 2) * HSS + i] = v2.z; Uc[(o4 * 4 + 3) * HSS + i] = v2.w;
    }

    // ---- seed g_h from h0 (og==0 CTAs write their bg slice)
    if (og == 0) {
        for (int idx = tid; idx < 8 * (H_DIM / 4); idx += 256) {
            int bl = idx >> 7, kq = idx & 127;
            float4 v = *(const float4*)(h0 + (size_t)(bg * 8 + bl) * H_DIM + kq * 4);
            __stcg((float4*)(g_h + (size_t)(bg * 8 + bl) * H_DIM + kq * 4), v);
        }
    }
    __threadfence();
    bg_barrier(bg);

    float hn_last = 0.f;

    for (int t = 0; t < S_LEN; ++t) {
        // ---- stage h slice [8][512] -> hS
        for (int idx = tid; idx < 1024; idx += 256) {
            int bl = idx >> 7, kq = idx & 127;
            float4 v = __ldcg((const float4*)(g_h + (size_t)(bg * 8 + bl) * H_DIM + kq * 4));
            *(float4*)&hS[bl * HSS + kq * 4] = v;
        }
        __syncthreads();

        // ---- phase 1: gate = w>>2 (0:r, 1:z), full k chain, 4 accumulators
        float hold;
        {
            const float* Ug = (w < 4) ? Ur : Uz;
            const float* hrow = &hS[b_loc * HSS];
            const float* urow = &Ug[o_idx * HSS];
            float a0 = 0.f, a1 = 0.f, a2 = 0.f, a3 = 0.f;
            #pragma unroll 8
            for (int kq = 0; kq < 128; kq++) {
                float4 hv = *(const float4*)&hrow[kq * 4];
                float4 uv = *(const float4*)&urow[kq * 4];
                a0 = fmaf(hv.x, uv.x, a0);
                a1 = fmaf(hv.y, uv.y, a1);
                a2 = fmaf(hv.z, uv.z, a2);
                a3 = fmaf(hv.w, uv.w, a3);
            }
            float sum = (a0 + a1) + (a2 + a3);
            int gate = w >> 2;
            float av = __ldg(&A[(size_t)(t * B_SZ + b) * 1536 + gate * H_DIM + o]);
            float sg = 1.f / (1.f + __expf(-(sum + av)));
            hold = hS[b_loc * HSS + o];
            if (gate == 0) {
                __stcg(&g_rh[(size_t)b * H_DIM + o], sg * hold);
            } else {
                zS[b_loc * 17 + o_idx] = sg;
            }
        }
        __threadfence();
        bg_barrier(bg);

        // ---- stage rh slice -> hS (hold survives in registers)
        for (int idx = tid; idx < 1024; idx += 256) {
            int bl = idx >> 7, kq = idx & 127;
            float4 v = __ldcg((const float4*)(g_rh + (size_t)(bg * 8 + bl) * H_DIM + kq * 4));
            *(float4*)&hS[bl * HSS + kq * 4] = v;
        }
        __syncthreads();

        // ---- phase 2: candidate, k split in halves across warp pairs
        {
            int khalf = (w >> 2) * 256;
            const float* hrow = &hS[b_loc * HSS + khalf];
            const float* urow = &Uc[o_idx * HSS + khalf];
            float a0 = 0.f, a1 = 0.f, a2 = 0.f, a3 = 0.f;
            #pragma unroll 8
            for (int kq = 0; kq < 64; kq++) {
                float4 hv = *(const float4*)&hrow[kq * 4];
                float4 uv = *(const float4*)&urow[kq * 4];
                a0 = fmaf(hv.x, uv.x, a0);
                a1 = fmaf(hv.y, uv.y, a1);
                a2 = fmaf(hv.z, uv.z, a2);
                a3 = fmaf(hv.w, uv.w, a3);
            }
            float partial = (a0 + a1) + (a2 + a3);
            if (w >= 4) redS[(w - 4) * 32 + lane] = partial;
            __syncthreads();
            if (w < 4) {
                float total = partial + redS[w * 32 + lane];
                float av = __ldg(&A[(size_t)(t * B_SZ + b) * 1536 + 2 * H_DIM + o]);
                float hh = tanhf(total + av);
                float z  = zS[b_loc * 17 + o_idx];
                float hn = fmaf(z, hh - hold, hold);
                hn_last = hn;
                __stcg(&g_h[(size_t)b * H_DIM + o], hn);
                __stcg(&Y[(size_t)(t * B_SZ + b) * H_DIM + o], hn);
            }
        }
        __threadfence();
        bg_barrier(bg);
    }

    if (w < 4) h_final[(size_t)b * H_DIM + o] = hn_last;
}

// ---------------- launch ----------------
extern "C" void kernel_launch(void* const* d_in, const int* in_sizes, int n_in,
                              void* d_out, int out_size) {
    const void*  tokens = d_in[0];
    const float* h0  = (const float*)d_in[1];
    const float* emb = (const float*)d_in[2];
    const float* Wx  = (const float*)d_in[3];
    const float* bx  = (const float*)d_in[4];
    const float* U   = (const float*)d_in[5];
    const float* Wy  = (const float*)d_in[6];
    const float* by  = (const float*)d_in[7];

    float* logits = (float*)d_out;                              // [S,B,V]
    float* hfin   = logits + (size_t)S_LEN * B_SZ * V_SZ;       // [L,B,H]

    float *dX, *dY, *dA;
    cudaGetSymbolAddress((void**)&dX, g_X);
    cudaGetSymbolAddress((void**)&dY, g_Y);
    cudaGetSymbolAddress((void**)&dA, g_A);

    const int M = S_LEN * B_SZ;
    const int RSMEM = (3 * 16 * HSS + 8 * HSS + 136 + 128) * 4;   // ~116.9 KB
    cudaFuncSetAttribute(recur_kernel, cudaFuncAttributeMaxDynamicSharedMemorySize, RSMEM);

    dim3 blk(256);

    detect_kernel<<<1, 32>>>((const int*)tokens);
    embed_kernel<<<M, 128>>>(tokens, emb, dX);

    // A0 = X @ Wx[0] + bx[0] (fused 3 gates)
    gemm_ax<<<dim3(12, M / 128), blk>>>(dX, Wx, bx, dA);

    // layer-0 recurrence
    recur_kernel<<<128, 256, RSMEM>>>(dA, U, h0, dY, hfin);

    // A1 = Y @ Wx[1] + bx[1]
    gemm_ax<<<dim3(12, M / 128), blk>>>(dY, Wx + (size_t)3 * H_DIM * H_DIM,
                                        bx + 3 * H_DIM, dA);

    // layer-1 recurrence
    recur_kernel<<<128, 256, RSMEM>>>(dA, U + (size_t)3 * H_DIM * H_DIM,
                                      h0 + B_SZ * H_DIM, dX, hfin + B_SZ * H_DIM);

    // logits = tops @ Wy^T + by
    gemm_bt<<<dim3((V_SZ + 127) / 128, M / 128), blk>>>(dX, Wy, by, logits, V_SZ);
}

// round 6
// speedup vs baseline: 1.9089x; 1.2018x over previous
#include <cuda_runtime.h>
#include <cstdint>

#define S_LEN 128
#define B_SZ  32
#define H_DIM 512
#define V_SZ  10000

typedef unsigned long long u64;

// ---------------- scratch (device globals; no allocation allowed) ----------------
__device__ float g_X[S_LEN * B_SZ * H_DIM];       // layer input / tops (8 MB)
__device__ float g_Y[S_LEN * B_SZ * H_DIM];       // layer-0 outputs (8 MB)
__device__ float g_A[S_LEN * B_SZ * 3 * H_DIM];   // precomputed x@Wx+bx (24 MB)
__device__ float g_h[B_SZ * H_DIM];               // h  [b][k]
__device__ float g_rh[B_SZ * H_DIM];              // r*h [b][k]
__device__ int   g_is64;

// ---------------- per-batch-group grid barrier (32 CTAs each, flat) -------------
__device__ unsigned          g_cnt2[4 * 32];
__device__ volatile unsigned g_gen2[4 * 32];

__device__ __forceinline__ void bg_barrier(int bg) {
    __syncthreads();
    if (threadIdx.x == 0) {
        volatile unsigned* genp = &g_gen2[bg * 32];
        unsigned* cntp = &g_cnt2[bg * 32];
        unsigned gen = *genp;
        __threadfence();   // release: covers whole CTA's prior stores (via __syncthreads chain)
        if (atomicAdd(cntp, 1u) == 31u) {
            *cntp = 0;
            __threadfence();
            *genp = gen + 1;
        } else {
            unsigned it = 0;
            while (*genp == gen) {
                if (++it > 65536u) { __nanosleep(32); }
                if (it > 400000u) break;   // safety valve: terminate, never hang
            }
        }
        __threadfence();   // acquire
    }
    __syncthreads();
}

// ---------------- token dtype detector ----------------
__global__ void detect_kernel(const int* __restrict__ t32) {
    if (threadIdx.x == 0 && blockIdx.x == 0) {
        unsigned o = 0;
        for (int i = 0; i < 128; i++) o |= (unsigned)t32[2 * i + 1];
        g_is64 = (o == 0) ? 1 : 0;   // all high words zero -> int64
    }
}

// ---------------- embedding gather (dtype-robust, clamped) ----------------
__global__ void embed_kernel(const void* __restrict__ tok,
                             const float* __restrict__ emb,
                             float* __restrict__ X) {
    int row = blockIdx.x;
    long long t;
    if (g_is64) t = ((const long long*)tok)[row];
    else        t = (long long)((const int*)tok)[row];
    if (t < 0) t = 0;
    if (t >= V_SZ) t = V_SZ - 1;
    const float4* src = (const float4*)(emb + (size_t)t * H_DIM);
    float4* dst = (float4*)(X + (size_t)row * H_DIM);
    for (int i = threadIdx.x; i < H_DIM / 4; i += blockDim.x) dst[i] = src[i];
}

// ---------------- tf32 mma + cp.async helpers ----------------
#define BM 128
#define BN 128
#define BKK 16
#define AST 20
#define BST_KN 136
#define BST_NK 20

__device__ __forceinline__ unsigned f2tf(float x) {
    unsigned r; asm("cvt.rna.tf32.f32 %0, %1;" : "=r"(r) : "f"(x)); return r;
}
__device__ __forceinline__ void mma8(float* c, const unsigned* a, const unsigned* b) {
    asm volatile(
        "mma.sync.aligned.m16n8k8.row.col.f32.tf32.tf32.f32 "
        "{%0,%1,%2,%3}, {%4,%5,%6,%7}, {%8,%9}, {%0,%1,%2,%3};\n"
        : "+f"(c[0]), "+f"(c[1]), "+f"(c[2]), "+f"(c[3])
        : "r"(a[0]), "r"(a[1]), "r"(a[2]), "r"(a[3]), "r"(b[0]), "r"(b[1]));
}
__device__ __forceinline__ void cpa16(unsigned dst, const void* src, bool pred) {
    int sz = pred ? 16 : 0;
    asm volatile("cp.async.cg.shared.global [%0], [%1], 16, %2;\n"
                 :: "r"(dst), "l"(src), "r"(sz));
}
__device__ __forceinline__ void cpa_commit() {
    asm volatile("cp.async.commit_group;\n" ::: "memory");
}
__device__ __forceinline__ void cpa_wait1() {
    asm volatile("cp.async.wait_group 1;\n" ::: "memory");
}
__device__ __forceinline__ unsigned smem_u32(const void* p) {
    return (unsigned)__cvta_generic_to_shared(p);
}

// packed fp32x2 fma (FFMA2) — full fp32 precision, half the issue count
__device__ __forceinline__ void fma2(u64& acc, u64 a, u64 b) {
    asm("fma.rn.f32x2 %0, %1, %2, %0;" : "+l"(acc) : "l"(a), "l"(b));
}
__device__ __forceinline__ float acc_sum(u64 a) {
    unsigned lo, hi;
    asm("mov.b64 {%0,%1}, %2;" : "=r"(lo), "=r"(hi) : "l"(a));
    return __uint_as_float(lo) + __uint_as_float(hi);
}

// ---------- fused 3-gate input GEMM: C[row][g*512+o] = X@Wx[g] + bx[g] ----------
__global__ __launch_bounds__(256, 2)
void gemm_ax(const float* __restrict__ A,          // X [M,512]
             const float* __restrict__ Wxl,        // [3,512,512]
             const float* __restrict__ bxl,        // [3,512]
             float* __restrict__ C) {              // [M,1536]
    __shared__ float As[2][BM * AST];
    __shared__ float Bs[2][BKK * BST_KN];

    int tid = threadIdx.x;
    int lane = tid & 31, warp = tid >> 5;
    int wr = warp >> 2, wc = warp & 3;
    int m0 = blockIdx.y * BM, n0 = blockIdx.x * BN;
    int g = n0 >> 9, col0 = n0 & 511;
    const float* Bg = Wxl + (size_t)g * H_DIM * H_DIM;

    // loader coordinates (invariant)
    const int ra = tid >> 1, ha = tid & 1;         // A tile
    const int krb = tid >> 4, csb = tid & 15;      // B tile (KN)
    const float* Asrc = A + (size_t)(m0 + ra) * H_DIM + ha * 8;
    const float* Bsrc = Bg + (size_t)krb * H_DIM + col0 + csb * 8;

    float c[4][4][4];
    #pragma unroll
    for (int i = 0; i < 4; i++)
        #pragma unroll
        for (int j = 0; j < 4; j++)
            #pragma unroll
            for (int k = 0; k < 4; k++) c[i][j][k] = 0.f;

    const int NK = H_DIM / BKK;
    // prologue: stage 0
    {
        unsigned da0 = smem_u32(&As[0][ra * AST + ha * 8]);
        cpa16(da0, Asrc, true); cpa16(da0 + 16, Asrc + 4, true);
        unsigned db0 = smem_u32(&Bs[0][krb * BST_KN + csb * 8]);
        cpa16(db0, Bsrc, true); cpa16(db0 + 16, Bsrc + 4, true);
        cpa_commit();
    }

    for (int it = 0; it < NK; it++) {
        if (it + 1 < NK) {
            int kk = (it + 1) * BKK, buf = (it + 1) & 1;
            unsigned da = smem_u32(&As[buf][ra * AST + ha * 8]);
            cpa16(da, Asrc + kk, true); cpa16(da + 16, Asrc + kk + 4, true);
            unsigned db = smem_u32(&Bs[buf][krb * BST_KN + csb * 8]);
            cpa16(db, Bsrc + (size_t)kk * H_DIM, true);
            cpa16(db + 16, Bsrc + (size_t)kk * H_DIM + 4, true);
        }
        cpa_commit();
        cpa_wait1();
        __syncthreads();

        const float* Ab = As[it & 1];
        const float* Bb = Bs[it & 1];
        int ar = lane >> 2, ak = lane & 3;
        #pragma unroll
        for (int kq = 0; kq < BKK; kq += 8) {
            unsigned af[4][4], bf[4][2];
            #pragma unroll
            for (int mt = 0; mt < 4; mt++) {
                int rb = wr * 64 + mt * 16;
                af[mt][0] = f2tf(Ab[(rb + ar)     * AST + kq + ak]);
                af[mt][1] = f2tf(Ab[(rb + ar + 8) * AST + kq + ak]);
                af[mt][2] = f2tf(Ab[(rb + ar)     * AST + kq + ak + 4]);
                af[mt][3] = f2tf(Ab[(rb + ar + 8) * AST + kq + ak + 4]);
            }
            #pragma unroll
            for (int nt = 0; nt < 4; nt++) {
                int cb = wc * 32 + nt * 8 + (lane >> 2);
                bf[nt][0] = f2tf(Bb[(kq + ak)     * BST_KN + cb]);
                bf[nt][1] = f2tf(Bb[(kq + ak + 4) * BST_KN + cb]);
            }
            #pragma unroll
            for (int mt = 0; mt < 4; mt++)
                #pragma unroll
                for (int nt = 0; nt < 4; nt++)
                    mma8(c[mt][nt], af[mt], bf[nt]);
        }
        __syncthreads();
    }

    #pragma unroll
    for (int mt = 0; mt < 4; mt++) {
        #pragma unroll
        for (int nt = 0; nt < 4; nt++) {
            int r0 = m0 + wr * 64 + mt * 16 + (lane >> 2);
            int cc = n0 + wc * 32 + nt * 8 + (lane & 3) * 2;
            float bv0 = bxl[g * H_DIM + (cc & 511)];
            float bv1 = bxl[g * H_DIM + ((cc + 1) & 511)];
            C[(size_t)r0 * 1536 + cc]           = c[mt][nt][0] + bv0;
            C[(size_t)r0 * 1536 + cc + 1]       = c[mt][nt][1] + bv1;
            C[(size_t)(r0 + 8) * 1536 + cc]     = c[mt][nt][2] + bv0;
            C[(size_t)(r0 + 8) * 1536 + cc + 1] = c[mt][nt][3] + bv1;
        }
    }
}

// ---------------- logits GEMM: C[M,N] = A[M,K] * B^T + bias (B:[N,K]) ----------
__global__ __launch_bounds__(256, 2)
void gemm_bt(const float* __restrict__ A,
             const float* __restrict__ Bm,
             const float* __restrict__ bias,
             float* __restrict__ C, int N) {
    __shared__ float As[2][BM * AST];
    __shared__ float Bs[2][BM * BST_NK];

    int tid = threadIdx.x;
    int lane = tid & 31, warp = tid >> 5;
    int wr = warp >> 2, wc = warp & 3;
    int m0 = blockIdx.y * BM, n0 = blockIdx.x * BN;

    const int ra = tid >> 1, ha = tid & 1;
    const int gn = n0 + ra;
    const bool bok = (gn < N);
    const float* Asrc = A + (size_t)(m0 + ra) * H_DIM + ha * 8;
    const float* Bsrc = Bm + (size_t)(bok ? gn : 0) * H_DIM + ha * 8;

    float c[4][4][4];
    #pragma unroll
    for (int i = 0; i < 4; i++)
        #pragma unroll
        for (int j = 0; j < 4; j++)
            #pragma unroll
            for (int k = 0; k < 4; k++) c[i][j][k] = 0.f;

    const int NK = H_DIM / BKK;
    {
        unsigned da = smem_u32(&As[0][ra * AST + ha * 8]);
        cpa16(da, Asrc, true); cpa16(da + 16, Asrc + 4, true);
        unsigned db = smem_u32(&Bs[0][ra * BST_NK + ha * 8]);
        cpa16(db, Bsrc, bok); cpa16(db + 16, Bsrc + 4, bok);
        cpa_commit();
    }

    for (int it = 0; it < NK; it++) {
        if (it + 1 < NK) {
            int kk = (it + 1) * BKK, buf = (it + 1) & 1;
            unsigned da = smem_u32(&As[buf][ra * AST + ha * 8]);
            cpa16(da, Asrc + kk, true); cpa16(da + 16, Asrc + kk + 4, true);
            unsigned db = smem_u32(&Bs[buf][ra * BST_NK + ha * 8]);
            cpa16(db, Bsrc + kk, bok); cpa16(db + 16, Bsrc + kk + 4, bok);
        }
        cpa_commit();
        cpa_wait1();
        __syncthreads();

        const float* Ab = As[it & 1];
        const float* Bb = Bs[it & 1];
        int ar = lane >> 2, ak = lane & 3;
        #pragma unroll
        for (int kq = 0; kq < BKK; kq += 8) {
            unsigned af[4][4], bf[4][2];
            #pragma unroll
            for (int mt = 0; mt < 4; mt++) {
                int rb = wr * 64 + mt * 16;
                af[mt][0] = f2tf(Ab[(rb + ar)     * AST + kq + ak]);
                af[mt][1] = f2tf(Ab[(rb + ar + 8) * AST + kq + ak]);
                af[mt][2] = f2tf(Ab[(rb + ar)     * AST + kq + ak + 4]);
                af[mt][3] = f2tf(Ab[(rb + ar + 8) * AST + kq + ak + 4]);
            }
            #pragma unroll
            for (int nt = 0; nt < 4; nt++) {
                int cb = wc * 32 + nt * 8 + (lane >> 2);
                bf[nt][0] = f2tf(Bb[cb * BST_NK + kq + ak]);
                bf[nt][1] = f2tf(Bb[cb * BST_NK + kq + ak + 4]);
            }
            #pragma unroll
            for (int mt = 0; mt < 4; mt++)
                #pragma unroll
                for (int nt = 0; nt < 4; nt++)
                    mma8(c[mt][nt], af[mt], bf[nt]);
        }
        __syncthreads();
    }

    #pragma unroll
    for (int mt = 0; mt < 4; mt++) {
        #pragma unroll
        for (int nt = 0; nt < 4; nt++) {
            int r0 = m0 + wr * 64 + mt * 16 + (lane >> 2);
            int cc = n0 + wc * 32 + nt * 8 + (lane & 3) * 2;
            if (cc < N) {
                float bv = bias[cc];
                C[(size_t)r0 * N + cc]       = c[mt][nt][0] + bv;
                C[(size_t)(r0 + 8) * N + cc] = c[mt][nt][2] + bv;
            }
            if (cc + 1 < N) {
                float bv = bias[cc + 1];
                C[(size_t)r0 * N + cc + 1]       = c[mt][nt][1] + bv;
                C[(size_t)(r0 + 8) * N + cc + 1] = c[mt][nt][3] + bv;
            }
        }
    }
}

// ---------------- persistent GRU recurrence (one layer, 128 CTAs) ----------------
// CTA = (bg 0..3, og 0..31): 8 batches x 16 outputs. lane = (o_loc 0..3, b_loc 0..7).
#define HSS 516
__global__ __launch_bounds__(256)
void recur_kernel(const float* __restrict__ A, const float* __restrict__ U,
                  const float* __restrict__ h0, float* __restrict__ Y,
                  float* __restrict__ h_final) {
    extern __shared__ float smem[];
    float* Ur = smem;                   // 16*516
    float* Uz = Ur + 16 * HSS;
    float* Uc = Uz + 16 * HSS;
    float* hS = Uc + 16 * HSS;          // 8*516
    float* zS = hS + 8 * HSS;           // 8*17
    float* redS = zS + 136;             // 128

    const int tid = threadIdx.x, lane = tid & 31, w = tid >> 5;
    const int b_loc = lane & 7, o_loc = lane >> 3;
    const int og = blockIdx.x & 31, bg = blockIdx.x >> 5;
    const int o_idx = (w & 3) * 4 + o_loc;       // 0..15
    const int o = og * 16 + o_idx;
    const int b = bg * 8 + b_loc;
    const int gate = w >> 2;

    // ---- stage transposed U columns (once): Us[o_idx][i] = U[g][i][og*16+o_idx]
    for (int idx = tid; idx < 2048; idx += 256) {
        int i = idx >> 2, o4 = idx & 3;
        float4 v0 = *(const float4*)(U + (size_t)i * H_DIM + og * 16 + o4 * 4);
        float4 v1 = *(const float4*)(U + (size_t)H_DIM * H_DIM + (size_t)i * H_DIM + og * 16 + o4 * 4);
        float4 v2 = *(const float4*)(U + (size_t)2 * H_DIM * H_DIM + (size_t)i * H_DIM + og * 16 + o4 * 4);
        Ur[(o4 * 4 + 0) * HSS + i] = v0.x; Ur[(o4 * 4 + 1) * HSS + i] = v0.y;
        Ur[(o4 * 4 + 2) * HSS + i] = v0.z; Ur[(o4 * 4 + 3) * HSS + i] = v0.w;
        Uz[(o4 * 4 + 0) * HSS + i] = v1.x; Uz[(o4 * 4 + 1) * HSS + i] = v1.y;
        Uz[(o4 * 4 + 2) * HSS + i] = v1.z; Uz[(o4 * 4 + 3) * HSS + i] = v1.w;
        Uc[(o4 * 4 + 0) * HSS + i] = v2.x; Uc[(o4 * 4 + 1) * HSS + i] = v2.y;
        Uc[(o4 * 4 + 2) * HSS + i] = v2.z; Uc[(o4 * 4 + 3) * HSS + i] = v2.w;
    }

    // ---- seed g_h from h0 (og==0 CTAs write their bg slice)
    if (og == 0) {
        for (int idx = tid; idx < 8 * (H_DIM / 4); idx += 256) {
            int bl = idx >> 7, kq = idx & 127;
            float4 v = *(const float4*)(h0 + (size_t)(bg * 8 + bl) * H_DIM + kq * 4);
            __stcg((float4*)(g_h + (size_t)(bg * 8 + bl) * H_DIM + kq * 4), v);
        }
    }
    bg_barrier(bg);

    float hn_last = 0.f;

    for (int t = 0; t < S_LEN; ++t) {
        // prefetch A operands for this step (hide DRAM/L2 latency behind staging)
        float av1 = __ldg(&A[(size_t)(t * B_SZ + b) * 1536 + gate * H_DIM + o]);
        float av2 = __ldg(&A[(size_t)(t * B_SZ + b) * 1536 + 2 * H_DIM + o]);

        // ---- stage h slice [8][512] -> hS
        for (int idx = tid; idx < 1024; idx += 256) {
            int bl = idx >> 7, kq = idx & 127;
            float4 v = __ldcg((const float4*)(g_h + (size_t)(bg * 8 + bl) * H_DIM + kq * 4));
            *(float4*)&hS[bl * HSS + kq * 4] = v;
        }
        __syncthreads();

        // ---- phase 1: gate = w>>2 (0:r, 1:z), packed f32x2 FMA
        float hold;
        {
            const float* Ug = (gate == 0) ? Ur : Uz;
            const float* hrow = &hS[b_loc * HSS];
            const float* urow = &Ug[o_idx * HSS];
            u64 a0 = 0ull, a1 = 0ull, a2 = 0ull, a3 = 0ull;
            #pragma unroll 8
            for (int kq = 0; kq < 128; kq += 2) {
                ulonglong2 hv0 = *(const ulonglong2*)&hrow[kq * 4];
                ulonglong2 uv0 = *(const ulonglong2*)&urow[kq * 4];
                ulonglong2 hv1 = *(const ulonglong2*)&hrow[kq * 4 + 4];
                ulonglong2 uv1 = *(const ulonglong2*)&urow[kq * 4 + 4];
                fma2(a0, hv0.x, uv0.x);
                fma2(a1, hv0.y, uv0.y);
                fma2(a2, hv1.x, uv1.x);
                fma2(a3, hv1.y, uv1.y);
            }
            float sum = (acc_sum(a0) + acc_sum(a1)) + (acc_sum(a2) + acc_sum(a3));
            float sg = 1.f / (1.f + __expf(-(sum + av1)));
            hold = hS[b_loc * HSS + o];
            if (gate == 0) {
                __stcg(&g_rh[(size_t)b * H_DIM + o], sg * hold);
            } else {
                zS[b_loc * 17 + o_idx] = sg;
            }
        }
        bg_barrier(bg);

        // ---- stage rh slice -> hS (hold survives in registers)
        for (int idx = tid; idx < 1024; idx += 256) {
            int bl = idx >> 7, kq = idx & 127;
            float4 v = __ldcg((const float4*)(g_rh + (size_t)(bg * 8 + bl) * H_DIM + kq * 4));
            *(float4*)&hS[bl * HSS + kq * 4] = v;
        }
        __syncthreads();

        // ---- phase 2: candidate, k split in halves across warp pairs
        {
            int khalf = gate * 256;
            const float* hrow = &hS[b_loc * HSS + khalf];
            const float* urow = &Uc[o_idx * HSS + khalf];
            u64 a0 = 0ull, a1 = 0ull, a2 = 0ull, a3 = 0ull;
            #pragma unroll 8
            for (int kq = 0; kq < 64; kq += 2) {
                ulonglong2 hv0 = *(const ulonglong2*)&hrow[kq * 4];
                ulonglong2 uv0 = *(const ulonglong2*)&urow[kq * 4];
                ulonglong2 hv1 = *(const ulonglong2*)&hrow[kq * 4 + 4];
                ulonglong2 uv1 = *(const ulonglong2*)&urow[kq * 4 + 4];
                fma2(a0, hv0.x, uv0.x);
                fma2(a1, hv0.y, uv0.y);
                fma2(a2, hv1.x, uv1.x);
                fma2(a3, hv1.y, uv1.y);
            }
            float partial = (acc_sum(a0) + acc_sum(a1)) + (acc_sum(a2) + acc_sum(a3));
            if (w >= 4) redS[(w - 4) * 32 + lane] = partial;
            __syncthreads();
            if (w < 4) {
                float total = partial + redS[w * 32 + lane];
                float hh = tanhf(total + av2);
                float z  = zS[b_loc * 17 + o_idx];
                float hn = fmaf(z, hh - hold, hold);
                hn_last = hn;
                __stcg(&g_h[(size_t)b * H_DIM + o], hn);
                __stcg(&Y[(size_t)(t * B_SZ + b) * H_DIM + o], hn);
            }
        }
        bg_barrier(bg);
    }

    if (w < 4) h_final[(size_t)b * H_DIM + o] = hn_last;
}

// ---------------- launch ----------------
extern "C" void kernel_launch(void* const* d_in, const int* in_sizes, int n_in,
                              void* d_out, int out_size) {
    const void*  tokens = d_in[0];
    const float* h0  = (const float*)d_in[1];
    const float* emb = (const float*)d_in[2];
    const float* Wx  = (const float*)d_in[3];
    const float* bx  = (const float*)d_in[4];
    const float* U   = (const float*)d_in[5];
    const float* Wy  = (const float*)d_in[6];
    const float* by  = (const float*)d_in[7];

    float* logits = (float*)d_out;                              // [S,B,V]
    float* hfin   = logits + (size_t)S_LEN * B_SZ * V_SZ;       // [L,B,H]

    float *dX, *dY, *dA;
    cudaGetSymbolAddress((void**)&dX, g_X);
    cudaGetSymbolAddress((void**)&dY, g_Y);
    cudaGetSymbolAddress((void**)&dA, g_A);

    const int M = S_LEN * B_SZ;
    const int RSMEM = (3 * 16 * HSS + 8 * HSS + 136 + 128) * 4;   // ~116.9 KB
    cudaFuncSetAttribute(recur_kernel, cudaFuncAttributeMaxDynamicSharedMemorySize, RSMEM);

    dim3 blk(256);

    detect_kernel<<<1, 32>>>((const int*)tokens);
    embed_kernel<<<M, 128>>>(tokens, emb, dX);

    // A0 = X @ Wx[0] + bx[0] (fused 3 gates)
    gemm_ax<<<dim3(12, M / 128), blk>>>(dX, Wx, bx, dA);

    // layer-0 recurrence
    recur_kernel<<<128, 256, RSMEM>>>(dA, U, h0, dY, hfin);

    // A1 = Y @ Wx[1] + bx[1]
    gemm_ax<<<dim3(12, M / 128), blk>>>(dY, Wx + (size_t)3 * H_DIM * H_DIM,
                                        bx + 3 * H_DIM, dA);

    // layer-1 recurrence
    recur_kernel<<<128, 256, RSMEM>>>(dA, U + (size_t)3 * H_DIM * H_DIM,
                                      h0 + B_SZ * H_DIM, dX, hfin + B_SZ * H_DIM);

    // logits = tops @ Wy^T + by
    gemm_bt<<<dim3((V_SZ + 127) / 128, M / 128), blk>>>(dX, Wy, by, logits, V_SZ);
}

// round 8
// speedup vs baseline: 2.1394x; 1.1208x over previous
#include <cuda_runtime.h>
#include <cstdint>

#define S_LEN 128
#define B_SZ  32
#define H_DIM 512
#define V_SZ  10000

typedef unsigned long long u64;

// ---------------- scratch (device globals; no allocation allowed) ----------------
__device__ float g_X[S_LEN * B_SZ * H_DIM];       // layer input / tops (8 MB)
__device__ float g_Y[S_LEN * B_SZ * H_DIM];       // layer-0 outputs (8 MB)
__device__ float g_A[S_LEN * B_SZ * 3 * H_DIM];   // precomputed x@Wx+bx (24 MB)
__device__ float g_h[B_SZ * H_DIM];               // h  [b][k]
__device__ float g_rh[B_SZ * H_DIM];              // r*h [b][k]
__device__ int   g_is64;

// ---------------- per-batch-group grid barrier (32 CTAs each, flat) -------------
__device__ unsigned          g_cnt2[4 * 32];
__device__ volatile unsigned g_gen2[4 * 32];

__device__ __forceinline__ void bg_barrier(int bg) {
    __syncthreads();
    if (threadIdx.x == 0) {
        volatile unsigned* genp = &g_gen2[bg * 32];
        unsigned* cntp = &g_cnt2[bg * 32];
        unsigned gen = *genp;
        __threadfence();
        if (atomicAdd(cntp, 1u) == 31u) {
            *cntp = 0;
            __threadfence();
            *genp = gen + 1;
        } else {
            unsigned it = 0;
            while (*genp == gen) {
                if (++it > 65536u) { __nanosleep(32); }
                if (it > 400000u) break;   // safety valve: terminate, never hang
            }
        }
        __threadfence();
    }
    __syncthreads();
}

// ---------------- token dtype detector ----------------
__global__ void detect_kernel(const int* __restrict__ t32) {
    if (threadIdx.x == 0 && blockIdx.x == 0) {
        unsigned o = 0;
        for (int i = 0; i < 128; i++) o |= (unsigned)t32[2 * i + 1];
        g_is64 = (o == 0) ? 1 : 0;
    }
}

// ---------------- embedding gather (dtype-robust, clamped) ----------------
__global__ void embed_kernel(const void* __restrict__ tok,
                             const float* __restrict__ emb,
                             float* __restrict__ X) {
    int row = blockIdx.x;
    long long t;
    if (g_is64) t = ((const long long*)tok)[row];
    else        t = (long long)((const int*)tok)[row];
    if (t < 0) t = 0;
    if (t >= V_SZ) t = V_SZ - 1;
    const float4* src = (const float4*)(emb + (size_t)t * H_DIM);
    float4* dst = (float4*)(X + (size_t)row * H_DIM);
    for (int i = threadIdx.x; i < H_DIM / 4; i += blockDim.x) dst[i] = src[i];
}

// ---------------- tf32 mma + cp.async helpers ----------------
#define BM 128
#define BN 128
#define BKK 16
#define AST 20
#define BST_KN 136
#define BST_NK 20

__device__ __forceinline__ unsigned f2tf(float x) {
    unsigned r; asm("cvt.rna.tf32.f32 %0, %1;" : "=r"(r) : "f"(x)); return r;
}
__device__ __forceinline__ void mma8(float* c, const unsigned* a, const unsigned* b) {
    asm volatile(
        "mma.sync.aligned.m16n8k8.row.col.f32.tf32.tf32.f32 "
        "{%0,%1,%2,%3}, {%4,%5,%6,%7}, {%8,%9}, {%0,%1,%2,%3};\n"
        : "+f"(c[0]), "+f"(c[1]), "+f"(c[2]), "+f"(c[3])
        : "r"(a[0]), "r"(a[1]), "r"(a[2]), "r"(a[3]), "r"(b[0]), "r"(b[1]));
}
__device__ __forceinline__ void cpa16(unsigned dst, const void* src, bool pred) {
    int sz = pred ? 16 : 0;
    asm volatile("cp.async.cg.shared.global [%0], [%1], 16, %2;\n"
                 :: "r"(dst), "l"(src), "r"(sz));
}
__device__ __forceinline__ void cpa_commit() {
    asm volatile("cp.async.commit_group;\n" ::: "memory");
}
__device__ __forceinline__ void cpa_wait1() {
    asm volatile("cp.async.wait_group 1;\n" ::: "memory");
}
__device__ __forceinline__ unsigned smem_u32(const void* p) {
    return (unsigned)__cvta_generic_to_shared(p);
}
__device__ __forceinline__ void fma2(u64& acc, u64 a, u64 b) {
    asm("fma.rn.f32x2 %0, %1, %2, %0;" : "+l"(acc) : "l"(a), "l"(b));
}
__device__ __forceinline__ float acc_sum(u64 a) {
    unsigned lo, hi;
    asm("mov.b64 {%0,%1}, %2;" : "=r"(lo), "=r"(hi) : "l"(a));
    return __uint_as_float(lo) + __uint_as_float(hi);
}

// ---------- fused 3-gate input GEMM (2-stage cp.async) --------------------------
__global__ __launch_bounds__(256, 2)
void gemm_ax(const float* __restrict__ A,          // X [M,512]
             const float* __restrict__ Wxl,        // [3,512,512]
             const float* __restrict__ bxl,        // [3,512]
             float* __restrict__ C) {              // [M,1536]
    __shared__ float As[2][BM * AST];
    __shared__ float Bs[2][BKK * BST_KN];

    int tid = threadIdx.x;
    int lane = tid & 31, warp = tid >> 5;
    int wr = warp >> 2, wc = warp & 3;
    int m0 = blockIdx.y * BM, n0 = blockIdx.x * BN;
    int g = n0 >> 9, col0 = n0 & 511;
    const float* Bg = Wxl + (size_t)g * H_DIM * H_DIM;

    const int ra = tid >> 1, ha = tid & 1;
    const int krb = tid >> 4, csb = tid & 15;
    const float* Asrc = A + (size_t)(m0 + ra) * H_DIM + ha * 8;
    const float* Bsrc = Bg + (size_t)krb * H_DIM + col0 + csb * 8;

    float c[4][4][4];
    #pragma unroll
    for (int i = 0; i < 4; i++)
        #pragma unroll
        for (int j = 0; j < 4; j++)
            #pragma unroll
            for (int k = 0; k < 4; k++) c[i][j][k] = 0.f;

    const int NK = H_DIM / BKK;
    {
        unsigned da0 = smem_u32(&As[0][ra * AST + ha * 8]);
        cpa16(da0, Asrc, true); cpa16(da0 + 16, Asrc + 4, true);
        unsigned db0 = smem_u32(&Bs[0][krb * BST_KN + csb * 8]);
        cpa16(db0, Bsrc, true); cpa16(db0 + 16, Bsrc + 4, true);
        cpa_commit();
    }

    for (int it = 0; it < NK; it++) {
        if (it + 1 < NK) {
            int kk = (it + 1) * BKK, buf = (it + 1) & 1;
            unsigned da = smem_u32(&As[buf][ra * AST + ha * 8]);
            cpa16(da, Asrc + kk, true); cpa16(da + 16, Asrc + kk + 4, true);
            unsigned db = smem_u32(&Bs[buf][krb * BST_KN + csb * 8]);
            cpa16(db, Bsrc + (size_t)kk * H_DIM, true);
            cpa16(db + 16, Bsrc + (size_t)kk * H_DIM + 4, true);
        }
        cpa_commit();
        cpa_wait1();
        __syncthreads();

        const float* Ab = As[it & 1];
        const float* Bb = Bs[it & 1];
        int ar = lane >> 2, ak = lane & 3;
        #pragma unroll
        for (int kq = 0; kq < BKK; kq += 8) {
            unsigned af[4][4], bf[4][2];
            #pragma unroll
            for (int mt = 0; mt < 4; mt++) {
                int rb = wr * 64 + mt * 16;
                af[mt][0] = f2tf(Ab[(rb + ar)     * AST + kq + ak]);
                af[mt][1] = f2tf(Ab[(rb + ar + 8) * AST + kq + ak]);
                af[mt][2] = f2tf(Ab[(rb + ar)     * AST + kq + ak + 4]);
                af[mt][3] = f2tf(Ab[(rb + ar + 8) * AST + kq + ak + 4]);
            }
            #pragma unroll
            for (int nt = 0; nt < 4; nt++) {
                int cb = wc * 32 + nt * 8 + (lane >> 2);
                bf[nt][0] = f2tf(Bb[(kq + ak)     * BST_KN + cb]);
                bf[nt][1] = f2tf(Bb[(kq + ak + 4) * BST_KN + cb]);
            }
            #pragma unroll
            for (int mt = 0; mt < 4; mt++)
                #pragma unroll
                for (int nt = 0; nt < 4; nt++)
                    mma8(c[mt][nt], af[mt], bf[nt]);
        }
        __syncthreads();
    }

    #pragma unroll
    for (int mt = 0; mt < 4; mt++) {
        #pragma unroll
        for (int nt = 0; nt < 4; nt++) {
            int r0 = m0 + wr * 64 + mt * 16 + (lane >> 2);
            int cc = n0 + wc * 32 + nt * 8 + (lane & 3) * 2;
            float bv0 = bxl[g * H_DIM + (cc & 511)];
            float bv1 = bxl[g * H_DIM + ((cc + 1) & 511)];
            C[(size_t)r0 * 1536 + cc]           = c[mt][nt][0] + bv0;
            C[(size_t)r0 * 1536 + cc + 1]       = c[mt][nt][1] + bv1;
            C[(size_t)(r0 + 8) * 1536 + cc]     = c[mt][nt][2] + bv0;
            C[(size_t)(r0 + 8) * 1536 + cc + 1] = c[mt][nt][3] + bv1;
        }
    }
}

// ---------------- logits GEMM, 3-stage cp.async pipeline ------------------------
#define GBUF 2560
__global__ __launch_bounds__(256, 2)
void gemm_bt(const float* __restrict__ A,
             const float* __restrict__ Bm,
             const float* __restrict__ bias,
             float* __restrict__ C, int N) {
    extern __shared__ float sm[];
    float* AsB = sm;              // 3 * 2560
    float* BsB = sm + 3 * GBUF;   // 3 * 2560

    int tid = threadIdx.x;
    int lane = tid & 31, warp = tid >> 5;
    int wr = warp >> 2, wc = warp & 3;
    int m0 = blockIdx.y * BM, n0 = blockIdx.x * BN;

    const int ra = tid >> 1, ha = tid & 1;
    const int gn = n0 + ra;
    const bool bok = (gn < N);
    const float* Asrc = A + (size_t)(m0 + ra) * H_DIM + ha * 8;
    const float* Bsrc = Bm + (size_t)(bok ? gn : 0) * H_DIM + ha * 8;

    float c[4][4][4];
    #pragma unroll
    for (int i = 0; i < 4; i++)
        #pragma unroll
        for (int j = 0; j < 4; j++)
            #pragma unroll
            for (int k = 0; k < 4; k++) c[i][j][k] = 0.f;

    const int NK = H_DIM / BKK;   // 32
    // prologue: stages 0 and 1 -> slots 0 and 1
    #pragma unroll
    for (int s = 0; s < 2; s++) {
        int kk = s * BKK;
        unsigned da = smem_u32(&AsB[s * GBUF + ra * AST + ha * 8]);
        cpa16(da, Asrc + kk, true); cpa16(da + 16, Asrc + kk + 4, true);
        unsigned db = smem_u32(&BsB[s * GBUF + ra * BST_NK + ha * 8]);
        cpa16(db, Bsrc + kk, bok); cpa16(db + 16, Bsrc + kk + 4, bok);
        cpa_commit();
    }

    int buf = 0;
    for (int it = 0; it < NK; it++) {
        cpa_wait1();
        __syncthreads();

        const float* Ab = &AsB[buf * GBUF];
        const float* Bb = &BsB[buf * GBUF];
        int ar = lane >> 2, ak = lane & 3;
        #pragma unroll
        for (int kq = 0; kq < BKK; kq += 8) {
            unsigned af[4][4], bf[4][2];
            #pragma unroll
            for (int mt = 0; mt < 4; mt++) {
                int rb = wr * 64 + mt * 16;
                af[mt][0] = f2tf(Ab[(rb + ar)     * AST + kq + ak]);
                af[mt][1] = f2tf(Ab[(rb + ar + 8) * AST + kq + ak]);
                af[mt][2] = f2tf(Ab[(rb + ar)     * AST + kq + ak + 4]);
                af[mt][3] = f2tf(Ab[(rb + ar + 8) * AST + kq + ak + 4]);
            }
            #pragma unroll
            for (int nt = 0; nt < 4; nt++) {
                int cb = wc * 32 + nt * 8 + (lane >> 2);
                bf[nt][0] = f2tf(Bb[cb * BST_NK + kq + ak]);
                bf[nt][1] = f2tf(Bb[cb * BST_NK + kq + ak + 4]);
            }
            #pragma unroll
            for (int mt = 0; mt < 4; mt++)
                #pragma unroll
                for (int nt = 0; nt < 4; nt++)
                    mma8(c[mt][nt], af[mt], bf[nt]);
        }
        __syncthreads();

        if (it + 2 < NK) {
            int kk = (it + 2) * BKK;
            int nb = (it + 2) % 3;     // FIX: stage s lives in slot s%3 (was nb=buf)
            unsigned da = smem_u32(&AsB[nb * GBUF + ra * AST + ha * 8]);
            cpa16(da, Asrc + kk, true); cpa16(da + 16, Asrc + kk + 4, true);
            unsigned db = smem_u32(&BsB[nb * GBUF + ra * BST_NK + ha * 8]);
            cpa16(db, Bsrc + kk, bok); cpa16(db + 16, Bsrc + kk + 4, bok);
        }
        cpa_commit();
        buf = (buf + 1) % 3;
    }

    #pragma unroll
    for (int mt = 0; mt < 4; mt++) {
        #pragma unroll
        for (int nt = 0; nt < 4; nt++) {
            int r0 = m0 + wr * 64 + mt * 16 + (lane >> 2);
            int cc = n0 + wc * 32 + nt * 8 + (lane & 3) * 2;
            if (cc < N) {
                float bv = bias[cc];
                C[(size_t)r0 * N + cc]       = c[mt][nt][0] + bv;
                C[(size_t)(r0 + 8) * N + cc] = c[mt][nt][2] + bv;
            }
            if (cc + 1 < N) {
                float bv = bias[cc + 1];
                C[(size_t)r0 * N + cc + 1]       = c[mt][nt][1] + bv;
                C[(size_t)(r0 + 8) * N + cc + 1] = c[mt][nt][3] + bv;
            }
        }
    }
}

// ---------------- persistent GRU recurrence (one layer, 128 CTAs) ----------------
// CTA = (bg, og): 8 batches x 16 outputs.
// Phase compute: warp = (k-quarter q = w&3, row-group rg = w>>2);
// lane = (slot = lane>>3, b = lane&7); each lane accumulates 4 rows (phase1) /
// 2x2 rows (phase2) over its k-quarter; k-quarters reduced via redS.
#define HSS 516
#define RST 36
__global__ __launch_bounds__(256)
void recur_kernel(const float* __restrict__ A, const float* __restrict__ U,
                  const float* __restrict__ h0, float* __restrict__ Y,
                  float* __restrict__ h_final) {
    extern __shared__ float smem[];
    float* hS    = smem;                    // 8*516
    float* Urz   = hS + 8 * HSS;            // 32*516 (rows 0-15: r, 16-31: z)
    float* Uc    = Urz + 32 * HSS;          // 16*516
    float* redS  = Uc + 16 * HSS;           // 32*36
    float* zS    = redS + 32 * RST;         // 128
    float* holdS = zS + 128;                // 128

    const int tid = threadIdx.x, lane = tid & 31, w = tid >> 5;
    const int q = w & 3, rg = w >> 2;
    const int slot = lane >> 3, bl = lane & 7;
    const int og = blockIdx.x & 31, bg = blockIdx.x >> 5;
    const int prow = tid >> 3, pb = tid & 7;

    // ---- stage transposed U (once): Urz[row][k], Uc[row][k]
    for (int idx = tid; idx < 2048; idx += 256) {
        int i = idx >> 2, o4 = idx & 3;
        float4 v0 = *(const float4*)(U + (size_t)i * H_DIM + og * 16 + o4 * 4);
        float4 v1 = *(const float4*)(U + (size_t)H_DIM * H_DIM + (size_t)i * H_DIM + og * 16 + o4 * 4);
        float4 v2 = *(const float4*)(U + (size_t)2 * H_DIM * H_DIM + (size_t)i * H_DIM + og * 16 + o4 * 4);
        Urz[(o4 * 4 + 0) * HSS + i] = v0.x; Urz[(o4 * 4 + 1) * HSS + i] = v0.y;
        Urz[(o4 * 4 + 2) * HSS + i] = v0.z; Urz[(o4 * 4 + 3) * HSS + i] = v0.w;
        Urz[(16 + o4 * 4 + 0) * HSS + i] = v1.x; Urz[(16 + o4 * 4 + 1) * HSS + i] = v1.y;
        Urz[(16 + o4 * 4 + 2) * HSS + i] = v1.z; Urz[(16 + o4 * 4 + 3) * HSS + i] = v1.w;
        Uc[(o4 * 4 + 0) * HSS + i] = v2.x; Uc[(o4 * 4 + 1) * HSS + i] = v2.y;
        Uc[(o4 * 4 + 2) * HSS + i] = v2.z; Uc[(o4 * 4 + 3) * HSS + i] = v2.w;
    }

    // ---- seed g_h from h0
    if (og == 0) {
        for (int idx = tid; idx < 8 * (H_DIM / 4); idx += 256) {
            int blr = idx >> 7, kq = idx & 127;
            float4 v = *(const float4*)(h0 + (size_t)(bg * 8 + blr) * H_DIM + kq * 4);
            __stcg((float4*)(g_h + (size_t)(bg * 8 + blr) * H_DIM + kq * 4), v);
        }
    }
    bg_barrier(bg);

    float hn_last = 0.f;

    for (int t = 0; t < S_LEN; ++t) {
        // prefetch A operands (mapped to finalize-thread roles)
        float av1 = __ldg(&A[(size_t)(t * B_SZ + bg * 8 + pb) * 1536 +
                             (prow < 16 ? 0 : 512) + og * 16 + (prow & 15)]);
        float av2 = (tid < 128)
            ? __ldg(&A[(size_t)(t * B_SZ + bg * 8 + pb) * 1536 + 1024 + og * 16 + prow])
            : 0.f;

        // ---- stage h slice [8][512] -> hS
        for (int idx = tid; idx < 1024; idx += 256) {
            int blr = idx >> 7, kq = idx & 127;
            float4 v = __ldcg((const float4*)(g_h + (size_t)(bg * 8 + blr) * H_DIM + kq * 4));
            *(float4*)&hS[blr * HSS + kq * 4] = v;
        }
        __syncthreads();

        // ---- phase 1 compute: rows rg*16 + slot + 4j, k-quarter q
        {
            const float* hb = hS + bl * HSS + q * 128;
            const float* ub = Urz + (size_t)(rg * 16 + slot) * HSS + q * 128;
            u64 a0 = 0ull, a1 = 0ull, a2 = 0ull, a3 = 0ull;
            #pragma unroll 4
            for (int c = 0; c < 32; c++) {
                ulonglong2 hv = *(const ulonglong2*)(hb + c * 4);
                ulonglong2 u0 = *(const ulonglong2*)(ub + c * 4);
                ulonglong2 u1 = *(const ulonglong2*)(ub + 4 * HSS + c * 4);
                ulonglong2 u2 = *(const ulonglong2*)(ub + 8 * HSS + c * 4);
                ulonglong2 u3 = *(const ulonglong2*)(ub + 12 * HSS + c * 4);
                fma2(a0, hv.x, u0.x); fma2(a1, hv.x, u1.x);
                fma2(a2, hv.x, u2.x); fma2(a3, hv.x, u3.x);
                fma2(a0, hv.y, u0.y); fma2(a1, hv.y, u1.y);
                fma2(a2, hv.y, u2.y); fma2(a3, hv.y, u3.y);
            }
            int rbase = rg * 16 + slot;
            redS[(rbase +  0) * RST + bl * 4 + q] = acc_sum(a0);
            redS[(rbase +  4) * RST + bl * 4 + q] = acc_sum(a1);
            redS[(rbase +  8) * RST + bl * 4 + q] = acc_sum(a2);
            redS[(rbase + 12) * RST + bl * 4 + q] = acc_sum(a3);
        }
        __syncthreads();

        // ---- phase 1 finalize (all 256 threads): row = prow, batch = pb
        {
            float4 p = *(const float4*)&redS[prow * RST + pb * 4];
            float sum = (p.x + p.y) + (p.z + p.w) + av1;
            float sg = 1.f / (1.f + __expf(-sum));
            if (prow < 16) {
                int o = og * 16 + prow;
                float hold = hS[pb * HSS + o];
                holdS[prow * 8 + pb] = hold;
                __stcg(&g_rh[(size_t)(bg * 8 + pb) * H_DIM + o], sg * hold);
            } else {
                zS[(prow - 16) * 8 + pb] = sg;
            }
        }
        bg_barrier(bg);

        // ---- stage rh slice -> hS
        for (int idx = tid; idx < 1024; idx += 256) {
            int blr = idx >> 7, kq = idx & 127;
            float4 v = __ldcg((const float4*)(g_rh + (size_t)(bg * 8 + blr) * H_DIM + kq * 4));
            *(float4*)&hS[blr * HSS + kq * 4] = v;
        }
        __syncthreads();

        // ---- phase 2 compute: rows rg*8 + slot + 4j (j=0,1), k-quarter q
        {
            const float* hb = hS + bl * HSS + q * 128;
            const float* ub = Uc + (size_t)(rg * 8 + slot) * HSS + q * 128;
            u64 a0x = 0ull, a0y = 0ull, a1x = 0ull, a1y = 0ull;
            #pragma unroll 4
            for (int c = 0; c < 32; c++) {
                ulonglong2 hv = *(const ulonglong2*)(hb + c * 4);
                ulonglong2 u0 = *(const ulonglong2*)(ub + c * 4);
                ulonglong2 u1 = *(const ulonglong2*)(ub + 4 * HSS + c * 4);
                fma2(a0x, hv.x, u0.x); fma2(a1x, hv.x, u1.x);
                fma2(a0y, hv.y, u0.y); fma2(a1y, hv.y, u1.y);
            }
            int rbase = rg * 8 + slot;
            redS[(rbase + 0) * RST + bl * 4 + q] = acc_sum(a0x) + acc_sum(a0y);
            redS[(rbase + 4) * RST + bl * 4 + q] = acc_sum(a1x) + acc_sum(a1y);
        }
        __syncthreads();

        // ---- phase 2 finalize (128 threads)
        if (tid < 128) {
            float4 p = *(const float4*)&redS[prow * RST + pb * 4];
            float hh = tanhf((p.x + p.y) + (p.z + p.w) + av2);
            float z = zS[prow * 8 + pb];
            float hold = holdS[prow * 8 + pb];
            float hn = fmaf(z, hh - hold, hold);
            hn_last = hn;
            __stcg(&g_h[(size_t)(bg * 8 + pb) * H_DIM + og * 16 + prow], hn);
            __stcg(&Y[(size_t)(t * B_SZ + bg * 8 + pb) * H_DIM + og * 16 + prow], hn);
        }
        bg_barrier(bg);
    }

    if (tid < 128)
        h_final[(size_t)(bg * 8 + pb) * H_DIM + og * 16 + prow] = hn_last;
}

// ---------------- launch ----------------
extern "C" void kernel_launch(void* const* d_in, const int* in_sizes, int n_in,
                              void* d_out, int out_size) {
    const void*  tokens = d_in[0];
    const float* h0  = (const float*)d_in[1];
    const float* emb = (const float*)d_in[2];
    const float* Wx  = (const float*)d_in[3];
    const float* bx  = (const float*)d_in[4];
    const float* U   = (const float*)d_in[5];
    const float* Wy  = (const float*)d_in[6];
    const float* by  = (const float*)d_in[7];

    float* logits = (float*)d_out;                              // [S,B,V]
    float* hfin   = logits + (size_t)S_LEN * B_SZ * V_SZ;       // [L,B,H]

    float *dX, *dY, *dA;
    cudaGetSymbolAddress((void**)&dX, g_X);
    cudaGetSymbolAddress((void**)&dY, g_Y);
    cudaGetSymbolAddress((void**)&dA, g_A);

    const int M = S_LEN * B_SZ;
    const int RSMEM = (8 * HSS + 32 * HSS + 16 * HSS + 32 * RST + 128 + 128) * 4;
    cudaFuncSetAttribute(recur_kernel, cudaFuncAttributeMaxDynamicSharedMemorySize, RSMEM);
    const int GSMEM = 6 * GBUF * 4;   // 61440
    cudaFuncSetAttribute(gemm_bt, cudaFuncAttributeMaxDynamicSharedMemorySize, GSMEM);

    dim3 blk(256);

    detect_kernel<<<1, 32>>>((const int*)tokens);
    embed_kernel<<<M, 128>>>(tokens, emb, dX);

    gemm_ax<<<dim3(12, M / 128), blk>>>(dX, Wx, bx, dA);

    recur_kernel<<<128, 256, RSMEM>>>(dA, U, h0, dY, hfin);

    gemm_ax<<<dim3(12, M / 128), blk>>>(dY, Wx + (size_t)3 * H_DIM * H_DIM,
                                        bx + 3 * H_DIM, dA);

    recur_kernel<<<128, 256, RSMEM>>>(dA, U + (size_t)3 * H_DIM * H_DIM,
                                      h0 + B_SZ * H_DIM, dX, hfin + B_SZ * H_DIM);

    gemm_bt<<<dim3((V_SZ + 127) / 128, M / 128), blk, GSMEM>>>(dX, Wy, by, logits, V_SZ);
}